// round 1
// baseline (speedup 1.0000x reference)
#include <cuda_runtime.h>

// NoTradeRegionRNN: D=2 channel RNN scan over T timesteps, B independent lanes.
// x, returns: (D, T, B) row-major  -> elem [d, t, b] at d*T*B + t*B + b
// output:     (D, T, B) followed by hT (D, 1, B) if out_size covers it.
//
// One thread per batch lane b. All loads/stores are coalesced (stride-1 in b).
// The recurrence carry (hx, hy) lives in registers; loads are independent of
// the carry so the compiler can hoist them ahead of the dependency chain.

__device__ __forceinline__ float relu_(float v) { return fmaxf(v, 0.0f); }

__global__ void __launch_bounds__(128, 8)
ntr_rnn_kernel(const float* __restrict__ x,
               const float* __restrict__ ret,
               const float* __restrict__ tgt,
               const float* __restrict__ wi,
               const float* __restrict__ wh,
               const float* __restrict__ bh,
               const float* __restrict__ w1,
               const float* __restrict__ w2,
               const float* __restrict__ wr,
               float* __restrict__ out,
               int T, int B, int write_hT)
{
    int b = blockIdx.x * blockDim.x + threadIdx.x;
    if (b >= B) return;

    // ---- broadcast scalar parameters (L1/L2-cached, uniform) ----
    const float wr00 = wr[0], wr01 = wr[1], wr10 = wr[2], wr11 = wr[3];
    const float bh0 = bh[0], bh1 = bh[1];
    const float t0 = tgt[0], t1 = tgt[1];
    const float Wi0 = wi[0], Wi1 = wi[1];
    const float Wh0 = wh[0], Wh1 = wh[1];
    const float W10 = w1[0], W11 = w1[1];
    const float W20 = w2[0], W21 = w2[1];

    const float ac = wr10 / wr00;
    const float bd = wr01 / wr11;

    // Corners: Corner[k] = w_rotate @ (s0[k]*bh0, s1[k]*bh1) + target
    // _IDX sign pattern: k0:(-,-) k1:(-,+) k2:(+,+) k3:(+,-)
    float Cx[4], Cy[4];
    {
        const float s0[4] = {-1.f, -1.f, 1.f, 1.f};
        const float s1[4] = {-1.f,  1.f, 1.f, -1.f};
#pragma unroll
        for (int k = 0; k < 4; ++k) {
            float vx = s0[k] * bh0;
            float vy = s1[k] * bh1;
            Cx[k] = wr00 * vx + wr01 * vy + t0;
            Cy[k] = wr10 * vx + wr11 * vy + t1;
        }
    }

    // ---- precompute the 4 bound-clamp constant triples ----
    const bool bdp = (bd >= 0.0f);
    const bool acp = (ac >= 0.0f);
    const float c_lbx = bdp ? Cy[0] : Cy[1];
    const float A_lbx = fabsf(Cx[1] - Cx[0]);
    const float o_lbx = bdp ? Cx[1] : Cx[0];

    const float c_ubx = bdp ? Cy[3] : Cy[2];
    const float A_ubx = fabsf(Cx[2] - Cx[3]);
    const float o_ubx = bdp ? Cx[2] : Cx[3];

    const float c_lby = acp ? Cx[0] : Cx[3];
    const float A_lby = fabsf(Cy[0] - Cy[3]);
    const float o_lby = acp ? Cy[3] : Cy[0];

    const float c_uby = acp ? Cx[1] : Cx[2];
    const float A_uby = fabsf(Cy[1] - Cy[2]);
    const float o_uby = acp ? Cy[2] : Cy[1];

    const size_t TB = (size_t)T * (size_t)B;
    const float* __restrict__ x0p = x + b;
    const float* __restrict__ x1p = x + TB + b;
    const float* __restrict__ r0p = ret + b;
    const float* __restrict__ r1p = ret + TB + b;
    float* __restrict__ o0p = out + b;
    float* __restrict__ o1p = out + TB + b;

    // h0 = x[:, 0, :]
    float hx = __ldg(x0p);
    float hy = __ldg(x1p);
    o0p[0] = hx;
    o1p[0] = hy;

#pragma unroll 4
    for (int t = 1; t < T; ++t) {
        // Independent of the carry -> compiler hoists these ahead of the chain.
        const size_t offp = (size_t)(t - 1) * (size_t)B;
        const size_t offt = (size_t)t * (size_t)B;
        float rx = __ldg(r0p + offp);
        float ry = __ldg(r1p + offp);
        float xx = __ldg(x0p + offt);
        float xy = __ldg(x1p + offt);

        // adj = h * (1+r) / (1 + h . r)
        float denom = fmaf(hx, rx, fmaf(hy, ry, 1.0f));
        float inv = __fdividef(1.0f, denom);
        float ax = hx * (1.0f + rx) * inv;
        float ay = hy * (1.0f + ry) * inv;

        // bounds from adjusted h
        float lbx = -relu_(fmaf(-1.0f, relu_((ay - c_lbx) * bd), A_lbx)) + o_lbx;
        float ubx = -relu_(fmaf(-1.0f, relu_((ay - c_ubx) * bd), A_ubx)) + o_ubx;
        float lby = -relu_(fmaf(-1.0f, relu_((ax - c_lby) * ac), A_lby)) + o_lby;
        float uby = -relu_(fmaf(-1.0f, relu_((ax - c_uby) * ac), A_uby)) + o_uby;

        // g1 = relu(Wi*x + Wh*adj - lb)
        float g1x = relu_(fmaf(Wi0, xx, fmaf(Wh0, ax, -lbx)));
        float g1y = relu_(fmaf(Wi1, xy, fmaf(Wh1, ay, -lby)));
        // g2 = relu(W1*g1 + ub - lb)
        float g2x = relu_(fmaf(W10, g1x, ubx - lbx));
        float g2y = relu_(fmaf(W11, g1y, uby - lby));
        // h = W2*g2 + ub
        hx = fmaf(W20, g2x, ubx);
        hy = fmaf(W21, g2y, uby);

        o0p[offt] = hx;
        o1p[offt] = hy;
    }

    if (write_hT) {
        out[2 * TB + b] = hx;
        out[2 * TB + B + b] = hy;
    }
}

extern "C" void kernel_launch(void* const* d_in, const int* in_sizes, int n_in,
                              void* d_out, int out_size)
{
    // metadata order:
    // 0 input (D,T,B), 1 target (D,), 2 returns_partition (D,T,B),
    // 3 hidden (D,1,B) [unused], 4 w_input, 5 w_hidden, 6 b_hidden,
    // 7 w_fc1, 8 w_fc2, 9 w_rotate (D,D)
    const float* x   = (const float*)d_in[0];
    const float* tgt = (const float*)d_in[1];
    const float* ret = (const float*)d_in[2];
    const float* wi  = (const float*)d_in[4];
    const float* wh  = (const float*)d_in[5];
    const float* bh  = (const float*)d_in[6];
    const float* w1  = (const float*)d_in[7];
    const float* w2  = (const float*)d_in[8];
    const float* wr  = (const float*)d_in[9];
    float* out = (float*)d_out;

    const int D = 2;
    const int B = in_sizes[3] / D;            // hidden is (D,1,B)
    const int T = in_sizes[0] / (D * B);      // input is (D,T,B)
    const int write_hT = (out_size >= D * T * B + D * B) ? 1 : 0;

    const int threads = 128;
    const int blocks = (B + threads - 1) / threads;
    ntr_rnn_kernel<<<blocks, threads>>>(x, ret, tgt, wi, wh, bh, w1, w2, wr,
                                        out, T, B, write_hT);
}

// round 2
// speedup vs baseline: 1.6163x; 1.6163x over previous
#include <cuda_runtime.h>

// NoTradeRegionRNN: D=2 channel RNN scan over T timesteps, B independent lanes.
// x, returns: (D, T, B) row-major  -> elem [d, t, b] at d*T*B + t*B + b
// output:     (D, T, B) followed by hT (D, 1, B) if out_size covers it.
//
// One thread per batch lane. The recurrence carry lives in registers; loads
// are independent of the carry, so we software-pipeline them with an explicit
// prefetch distance of PF steps (32 LDGs in flight per warp) to hide DRAM
// latency behind the serial per-step compute chain.

__device__ __forceinline__ float relu_(float v) { return fmaxf(v, 0.0f); }

constexpr int PF = 8;   // prefetch distance (steps)

__global__ void __launch_bounds__(128)
ntr_rnn_kernel(const float* __restrict__ x,
               const float* __restrict__ ret,
               const float* __restrict__ tgt,
               const float* __restrict__ wi,
               const float* __restrict__ wh,
               const float* __restrict__ bh,
               const float* __restrict__ w1,
               const float* __restrict__ w2,
               const float* __restrict__ wr,
               float* __restrict__ out,
               int T, int B, int write_hT)
{
    const int b = blockIdx.x * blockDim.x + threadIdx.x;
    if (b >= B) return;

    // ---- broadcast scalar parameters ----
    const float wr00 = wr[0], wr01 = wr[1], wr10 = wr[2], wr11 = wr[3];
    const float bh0 = bh[0], bh1 = bh[1];
    const float t0 = tgt[0], t1 = tgt[1];
    const float Wi0 = wi[0], Wi1 = wi[1];
    const float Wh0 = wh[0], Wh1 = wh[1];
    const float W10 = w1[0], W11 = w1[1];
    const float W20 = w2[0], W21 = w2[1];

    const float ac = wr10 / wr00;
    const float bd = wr01 / wr11;

    // Corners: Corner[k] = w_rotate @ (s0[k]*bh0, s1[k]*bh1) + target
    // _IDX sign pattern: k0:(-,-) k1:(-,+) k2:(+,+) k3:(+,-)
    float Cx[4], Cy[4];
    {
        const float s0[4] = {-1.f, -1.f, 1.f, 1.f};
        const float s1[4] = {-1.f,  1.f, 1.f, -1.f};
#pragma unroll
        for (int k = 0; k < 4; ++k) {
            float vx = s0[k] * bh0;
            float vy = s1[k] * bh1;
            Cx[k] = wr00 * vx + wr01 * vy + t0;
            Cy[k] = wr10 * vx + wr11 * vy + t1;
        }
    }

    // ---- bound-clamp constants; fold c into the fma: (h-c)*s = fma(h,s,-c*s)
    const bool bdp = (bd >= 0.0f);
    const bool acp = (ac >= 0.0f);

    const float m_lbx = -(bdp ? Cy[0] : Cy[1]) * bd;
    const float A_lbx = fabsf(Cx[1] - Cx[0]);
    const float o_lbx = bdp ? Cx[1] : Cx[0];

    const float m_ubx = -(bdp ? Cy[3] : Cy[2]) * bd;
    const float A_ubx = fabsf(Cx[2] - Cx[3]);
    const float o_ubx = bdp ? Cx[2] : Cx[3];

    const float m_lby = -(acp ? Cx[0] : Cx[3]) * ac;
    const float A_lby = fabsf(Cy[0] - Cy[3]);
    const float o_lby = acp ? Cy[3] : Cy[0];

    const float m_uby = -(acp ? Cx[1] : Cx[2]) * ac;
    const float A_uby = fabsf(Cy[1] - Cy[2]);
    const float o_uby = acp ? Cy[2] : Cy[1];

    const size_t TB = (size_t)T * (size_t)B;
    const float* __restrict__ x0p = x + b;
    const float* __restrict__ x1p = x + TB + b;
    const float* __restrict__ r0p = ret + b;
    const float* __restrict__ r1p = ret + TB + b;
    float* __restrict__ o0p = out + b;
    float* __restrict__ o1p = out + TB + b;

    // h0 = x[:, 0, :]
    float hx = __ldg(x0p);
    float hy = __ldg(x1p);
    o0p[0] = hx;
    o1p[0] = hy;

    const int STEPS = T - 1;

    // ---- prologue: fill the prefetch buffers for steps 0..PF-1 ----
    // step s uses returns at t=s and x at t=s+1.
    float fx[PF], fy[PF], fr0[PF], fr1[PF];
#pragma unroll
    for (int j = 0; j < PF; ++j) {
        int s = (j < STEPS) ? j : (STEPS - 1);
        size_t offr = (size_t)s * (size_t)B;
        size_t offx = (size_t)(s + 1) * (size_t)B;
        fr0[j] = __ldcs(r0p + offr);
        fr1[j] = __ldcs(r1p + offr);
        fx[j]  = __ldcs(x0p + offx);
        fy[j]  = __ldcs(x1p + offx);
    }

#define NTR_STEP(S, J, DO_PREFETCH)                                          \
    do {                                                                      \
        float rx = fr0[J], ry = fr1[J], xx = fx[J], xy = fy[J];               \
        if (DO_PREFETCH) {                                                    \
            int sp = (S) + PF; sp = (sp < STEPS) ? sp : (STEPS - 1);          \
            size_t offr = (size_t)sp * (size_t)B;                             \
            size_t offx = (size_t)(sp + 1) * (size_t)B;                       \
            fr0[J] = __ldcs(r0p + offr);                                      \
            fr1[J] = __ldcs(r1p + offr);                                      \
            fx[J]  = __ldcs(x0p + offx);                                      \
            fy[J]  = __ldcs(x1p + offx);                                      \
        }                                                                     \
        /* adj = h * (1+r) / (1 + h . r) */                                   \
        float denom = fmaf(hx, rx, fmaf(hy, ry, 1.0f));                       \
        float inv = __fdividef(1.0f, denom);                                  \
        float ax = hx * (1.0f + rx) * inv;                                    \
        float ay = hy * (1.0f + ry) * inv;                                    \
        /* bounds: lb = o - relu(A - relu(fma(a, slope, m))) */               \
        float lbx = o_lbx - relu_(A_lbx - relu_(fmaf(ay, bd, m_lbx)));        \
        float ubx = o_ubx - relu_(A_ubx - relu_(fmaf(ay, bd, m_ubx)));        \
        float lby = o_lby - relu_(A_lby - relu_(fmaf(ax, ac, m_lby)));        \
        float uby = o_uby - relu_(A_uby - relu_(fmaf(ax, ac, m_uby)));        \
        /* g1 = relu(Wi*x + Wh*adj - lb) */                                   \
        float g1x = relu_(fmaf(Wi0, xx, fmaf(Wh0, ax, -lbx)));                \
        float g1y = relu_(fmaf(Wi1, xy, fmaf(Wh1, ay, -lby)));                \
        /* g2 = relu(W1*g1 + ub - lb) */                                      \
        float g2x = relu_(fmaf(W10, g1x, ubx - lbx));                         \
        float g2y = relu_(fmaf(W11, g1y, uby - lby));                         \
        /* h = W2*g2 + ub */                                                  \
        hx = fmaf(W20, g2x, ubx);                                             \
        hy = fmaf(W21, g2y, uby);                                             \
        size_t offt = (size_t)((S) + 1) * (size_t)B;                          \
        __stcs(o0p + offt, hx);                                               \
        __stcs(o1p + offt, hy);                                               \
    } while (0)

    // ---- main loop: multiples of PF, fully unrolled, static buffer index ----
    int s = 0;
    const int main_end = STEPS & ~(PF - 1);
    for (; s < main_end; s += PF) {
#pragma unroll
        for (int j = 0; j < PF; ++j) {
            NTR_STEP(s + j, j, true);
        }
    }

    // ---- epilogue: < PF remaining steps, guarded, no prefetch ----
#pragma unroll
    for (int j = 0; j < PF; ++j) {
        if (s + j < STEPS) {
            NTR_STEP(s + j, j, false);
        }
    }
#undef NTR_STEP

    if (write_hT) {
        out[2 * TB + b] = hx;
        out[2 * TB + B + b] = hy;
    }
}

extern "C" void kernel_launch(void* const* d_in, const int* in_sizes, int n_in,
                              void* d_out, int out_size)
{
    // metadata order:
    // 0 input (D,T,B), 1 target (D,), 2 returns_partition (D,T,B),
    // 3 hidden (D,1,B) [unused], 4 w_input, 5 w_hidden, 6 b_hidden,
    // 7 w_fc1, 8 w_fc2, 9 w_rotate (D,D)
    const float* x   = (const float*)d_in[0];
    const float* tgt = (const float*)d_in[1];
    const float* ret = (const float*)d_in[2];
    const float* wi  = (const float*)d_in[4];
    const float* wh  = (const float*)d_in[5];
    const float* bh  = (const float*)d_in[6];
    const float* w1  = (const float*)d_in[7];
    const float* w2  = (const float*)d_in[8];
    const float* wr  = (const float*)d_in[9];
    float* out = (float*)d_out;

    const int D = 2;
    const int B = in_sizes[3] / D;            // hidden is (D,1,B)
    const int T = in_sizes[0] / (D * B);      // input is (D,T,B)
    const int write_hT = (out_size >= D * T * B + D * B) ? 1 : 0;

    const int threads = 128;
    const int blocks = (B + threads - 1) / threads;
    ntr_rnn_kernel<<<blocks, threads>>>(x, ret, tgt, wi, wh, bh, w1, w2, wr,
                                        out, T, B, write_hT);
}

// round 3
// speedup vs baseline: 2.4130x; 1.4929x over previous
#include <cuda_runtime.h>

// NoTradeRegionRNN: D=2 channel RNN scan, T timesteps, B independent lanes.
// x, returns: (D, T, B) row-major. output: (D, T, B) then hT (D, 1, B).
//
// One thread per lane; carry in registers. Specialized kernel for the bench
// shape (T=512, B=16384): all in-group offsets are compile-time immediates,
// prefetch distance PF=16 with a statically unrolled tail (zero runtime
// clamps). Bounds use the algebraic identity
//   o - relu(A - relu(w)) == clamp(w + o - A, o - A, o)
// which shortens each bound to FFMA + 2*FMNMX.

__device__ __forceinline__ float relu_(float v) { return fmaxf(v, 0.0f); }
__device__ __forceinline__ float clamp_(float v, float lo, float hi) {
    return fminf(fmaxf(v, lo), hi);
}

// ---------------- shared parameter block ----------------
struct Params {
    float ac, bd;
    float Wi0, Wi1, Wh0, Wh1, W10, W11, W20, W21;
    // clamp-form bound constants: val = clamp(fma(a, slope, C), LO, HI)
    float C_lbx, LO_lbx, HI_lbx;
    float C_ubx, LO_ubx, HI_ubx;
    float C_lby, LO_lby, HI_lby;
    float C_uby, LO_uby, HI_uby;
};

__device__ __forceinline__ Params make_params(
    const float* __restrict__ tgt, const float* __restrict__ wi,
    const float* __restrict__ wh,  const float* __restrict__ bh,
    const float* __restrict__ w1,  const float* __restrict__ w2,
    const float* __restrict__ wr)
{
    Params P;
    const float wr00 = wr[0], wr01 = wr[1], wr10 = wr[2], wr11 = wr[3];
    const float bh0 = bh[0], bh1 = bh[1];
    const float t0 = tgt[0], t1 = tgt[1];
    P.Wi0 = wi[0]; P.Wi1 = wi[1];
    P.Wh0 = wh[0]; P.Wh1 = wh[1];
    P.W10 = w1[0]; P.W11 = w1[1];
    P.W20 = w2[0]; P.W21 = w2[1];
    P.ac = wr10 / wr00;
    P.bd = wr01 / wr11;

    // Corners: k0:(-,-) k1:(-,+) k2:(+,+) k3:(+,-) applied to (bh0, bh1)
    float Cx[4], Cy[4];
    const float s0[4] = {-1.f, -1.f, 1.f, 1.f};
    const float s1[4] = {-1.f,  1.f, 1.f, -1.f};
#pragma unroll
    for (int k = 0; k < 4; ++k) {
        float vx = s0[k] * bh0, vy = s1[k] * bh1;
        Cx[k] = wr00 * vx + wr01 * vy + t0;
        Cy[k] = wr10 * vx + wr11 * vy + t1;
    }
    const bool bdp = (P.bd >= 0.0f);
    const bool acp = (P.ac >= 0.0f);

    // each bound: w = (a - c)*slope = fma(a, slope, -c*slope)
    // val = clamp(w + o - A, o - A, o)  ->  C = -c*slope + o - A, LO = o-A, HI = o
    {
        float c = bdp ? Cy[0] : Cy[1], A = fabsf(Cx[1] - Cx[0]), o = bdp ? Cx[1] : Cx[0];
        P.C_lbx = -c * P.bd + o - A; P.LO_lbx = o - A; P.HI_lbx = o;
    }
    {
        float c = bdp ? Cy[3] : Cy[2], A = fabsf(Cx[2] - Cx[3]), o = bdp ? Cx[2] : Cx[3];
        P.C_ubx = -c * P.bd + o - A; P.LO_ubx = o - A; P.HI_ubx = o;
    }
    {
        float c = acp ? Cx[0] : Cx[3], A = fabsf(Cy[0] - Cy[3]), o = acp ? Cy[3] : Cy[0];
        P.C_lby = -c * P.ac + o - A; P.LO_lby = o - A; P.HI_lby = o;
    }
    {
        float c = acp ? Cx[1] : Cx[2], A = fabsf(Cy[1] - Cy[2]), o = acp ? Cy[2] : Cy[1];
        P.C_uby = -c * P.ac + o - A; P.LO_uby = o - A; P.HI_uby = o;
    }
    return P;
}

// one recurrence step: carry (hx, hy), inputs (rx, ry, xx, xy)
__device__ __forceinline__ void ntr_step(const Params& P,
                                         float& hx, float& hy,
                                         float rx, float ry,
                                         float xx, float xy)
{
    float denom = fmaf(hx, rx, fmaf(hy, ry, 1.0f));
    float inv = __fdividef(1.0f, denom);
    float ax = hx * (1.0f + rx) * inv;
    float ay = hy * (1.0f + ry) * inv;

    float lbx = clamp_(fmaf(ay, P.bd, P.C_lbx), P.LO_lbx, P.HI_lbx);
    float ubx = clamp_(fmaf(ay, P.bd, P.C_ubx), P.LO_ubx, P.HI_ubx);
    float lby = clamp_(fmaf(ax, P.ac, P.C_lby), P.LO_lby, P.HI_lby);
    float uby = clamp_(fmaf(ax, P.ac, P.C_uby), P.LO_uby, P.HI_uby);

    float g1x = relu_(fmaf(P.Wi0, xx, fmaf(P.Wh0, ax, -lbx)));
    float g1y = relu_(fmaf(P.Wi1, xy, fmaf(P.Wh1, ay, -lby)));
    float g2x = relu_(fmaf(P.W10, g1x, ubx - lbx));
    float g2y = relu_(fmaf(P.W11, g1y, uby - lby));
    hx = fmaf(P.W20, g2x, ubx);
    hy = fmaf(P.W21, g2y, uby);
}

// ---------------- specialized kernel: compile-time T, B ----------------
template <int T, int B, int PF>
__global__ void __launch_bounds__(128)
ntr_rnn_static(const float* __restrict__ x,
               const float* __restrict__ ret,
               const float* __restrict__ tgt,
               const float* __restrict__ wi,
               const float* __restrict__ wh,
               const float* __restrict__ bh,
               const float* __restrict__ w1,
               const float* __restrict__ w2,
               const float* __restrict__ wr,
               float* __restrict__ out,
               int write_hT)
{
    const int b = blockIdx.x * blockDim.x + threadIdx.x;
    const Params P = make_params(tgt, wi, wh, bh, w1, w2, wr);

    constexpr int STEPS = T - 1;                    // 511
    constexpr int MAIN_END = ((STEPS - PF) / PF) * PF;  // last full-prefetch group start bound

    const size_t TB = (size_t)T * (size_t)B;

    // channel-plane pointers; step s reads r at t=s, x at t=s+1, writes t=s+1
    const float* r0 = ret + b;
    const float* r1 = ret + TB + b;
    const float* x0 = x + b + B;        // t = 1
    const float* x1 = x + TB + b + B;
    float* o0 = out + b + B;            // t = 1
    float* o1 = out + TB + b + B;

    // h0 = x[:, 0, :]
    float hx = __ldg(x + b);
    float hy = __ldg(x + TB + b);
    out[b] = hx;
    out[TB + b] = hy;

    // prologue: buffers for steps 0..PF-1 (all valid: STEPS > PF)
    float fr0[PF], fr1[PF], fx0[PF], fx1[PF];
#pragma unroll
    for (int j = 0; j < PF; ++j) {
        fr0[j] = __ldcs(r0 + (size_t)j * B);
        fr1[j] = __ldcs(r1 + (size_t)j * B);
        fx0[j] = __ldcs(x0 + (size_t)j * B);
        fx1[j] = __ldcs(x1 + (size_t)j * B);
    }

    // main loop: groups with unconditional prefetch (sp = s+j+PF <= STEPS-1)
    int s = 0;
    for (; s < MAIN_END; s += PF) {
#pragma unroll
        for (int j = 0; j < PF; ++j) {
            float rx = fr0[j], ry = fr1[j], xx = fx0[j], xy = fx1[j];
            // prefetch step s+j+PF : immediate offsets (j+PF)*B*4 < 8MB
            fr0[j] = __ldcs(r0 + (size_t)(j + PF) * B);
            fr1[j] = __ldcs(r1 + (size_t)(j + PF) * B);
            fx0[j] = __ldcs(x0 + (size_t)(j + PF) * B);
            fx1[j] = __ldcs(x1 + (size_t)(j + PF) * B);
            ntr_step(P, hx, hy, rx, ry, xx, xy);
            __stcs(o0 + (size_t)j * B, hx);
            __stcs(o1 + (size_t)j * B, hy);
        }
        r0 += (size_t)PF * B; r1 += (size_t)PF * B;
        x0 += (size_t)PF * B; x1 += (size_t)PF * B;
        o0 += (size_t)PF * B; o1 += (size_t)PF * B;
    }

    // tail group A: steps MAIN_END .. MAIN_END+PF-1, prefetch only where
    // target step < STEPS (compile-time guard per j).
    constexpr int REM_AFTER_A = STEPS - MAIN_END - PF;   // remaining steps after group A
#pragma unroll
    for (int j = 0; j < PF; ++j) {
        float rx = fr0[j], ry = fr1[j], xx = fx0[j], xy = fx1[j];
        if (j < REM_AFTER_A) {
            fr0[j] = __ldcs(r0 + (size_t)(j + PF) * B);
            fr1[j] = __ldcs(r1 + (size_t)(j + PF) * B);
            fx0[j] = __ldcs(x0 + (size_t)(j + PF) * B);
            fx1[j] = __ldcs(x1 + (size_t)(j + PF) * B);
        }
        ntr_step(P, hx, hy, rx, ry, xx, xy);
        __stcs(o0 + (size_t)j * B, hx);
        __stcs(o1 + (size_t)j * B, hy);
    }
    o0 += (size_t)PF * B; o1 += (size_t)PF * B;

    // tail group B: final REM_AFTER_A steps from buffers, no prefetch.
#pragma unroll
    for (int j = 0; j < PF; ++j) {
        if (j < REM_AFTER_A) {
            ntr_step(P, hx, hy, fr0[j], fr1[j], fx0[j], fx1[j]);
            __stcs(o0 + (size_t)j * B, hx);
            __stcs(o1 + (size_t)j * B, hy);
        }
    }

    if (write_hT) {
        out[2 * TB + b] = hx;
        out[2 * TB + B + b] = hy;
    }
}

// ---------------- generic fallback (any T, B) ----------------
__global__ void __launch_bounds__(128)
ntr_rnn_generic(const float* __restrict__ x,
                const float* __restrict__ ret,
                const float* __restrict__ tgt,
                const float* __restrict__ wi,
                const float* __restrict__ wh,
                const float* __restrict__ bh,
                const float* __restrict__ w1,
                const float* __restrict__ w2,
                const float* __restrict__ wr,
                float* __restrict__ out,
                int T, int B, int write_hT)
{
    const int b = blockIdx.x * blockDim.x + threadIdx.x;
    if (b >= B) return;
    const Params P = make_params(tgt, wi, wh, bh, w1, w2, wr);

    const size_t TB = (size_t)T * (size_t)B;
    const float* r0 = ret + b;
    const float* r1 = ret + TB + b;
    const float* x0 = x + b;
    const float* x1 = x + TB + b;
    float* o0 = out + b;
    float* o1 = out + TB + b;

    float hx = __ldg(x0);
    float hy = __ldg(x1);
    o0[0] = hx; o1[0] = hy;

    for (int t = 1; t < T; ++t) {
        size_t offp = (size_t)(t - 1) * B;
        size_t offt = (size_t)t * B;
        float rx = __ldcs(r0 + offp), ry = __ldcs(r1 + offp);
        float xx = __ldcs(x0 + offt), xy = __ldcs(x1 + offt);
        ntr_step(P, hx, hy, rx, ry, xx, xy);
        __stcs(o0 + offt, hx);
        __stcs(o1 + offt, hy);
    }
    if (write_hT) {
        out[2 * TB + b] = hx;
        out[2 * TB + B + b] = hy;
    }
}

extern "C" void kernel_launch(void* const* d_in, const int* in_sizes, int n_in,
                              void* d_out, int out_size)
{
    // 0 input (D,T,B), 1 target, 2 returns (D,T,B), 3 hidden (D,1,B),
    // 4 w_input, 5 w_hidden, 6 b_hidden, 7 w_fc1, 8 w_fc2, 9 w_rotate
    const float* x   = (const float*)d_in[0];
    const float* tgt = (const float*)d_in[1];
    const float* ret = (const float*)d_in[2];
    const float* wi  = (const float*)d_in[4];
    const float* wh  = (const float*)d_in[5];
    const float* bh  = (const float*)d_in[6];
    const float* w1  = (const float*)d_in[7];
    const float* w2  = (const float*)d_in[8];
    const float* wr  = (const float*)d_in[9];
    float* out = (float*)d_out;

    const int D = 2;
    const int B = in_sizes[3] / D;
    const int T = in_sizes[0] / (D * B);
    const int write_hT = (out_size >= D * T * B + D * B) ? 1 : 0;

    constexpr int TS = 512, BS = 16384, PF = 16;
    if (T == TS && B == BS) {
        const int threads = 128;
        const int blocks = BS / threads;
        ntr_rnn_static<TS, BS, PF><<<blocks, threads>>>(
            x, ret, tgt, wi, wh, bh, w1, w2, wr, out, write_hT);
    } else {
        const int threads = 128;
        const int blocks = (B + threads - 1) / threads;
        ntr_rnn_generic<<<blocks, threads>>>(
            x, ret, tgt, wi, wh, bh, w1, w2, wr, out, T, B, write_hT);
    }
}